// round 8
// baseline (speedup 1.0000x reference)
#include <cuda_runtime.h>
#include <cuda_bf16.h>
#include <math.h>
#include <stdint.h>

#define HW    56
#define NPIX  3136
#define CDIM  256
#define HEADS 8
#define HD    32
#define NPAIR 16
#define BATCH 2
#define MROWS (BATCH*NPIX)
#define WIN   7
#define RAD   3

__device__ float g_q[BATCH*HEADS*NPIX*HD];
__device__ float g_k[BATCH*HEADS*NPIX*HD];
__device__ float g_v[BATCH*HEADS*NPIX*HD];
__device__ float g_cos[NPIX*NPAIR];
__device__ float g_sin[NPIX*NPAIR];
__device__ __nv_bfloat16 g_Xhi[MROWS*CDIM];
__device__ __nv_bfloat16 g_Xlo[MROWS*CDIM];
__device__ __nv_bfloat16 g_Wqt_hi[768*CDIM];
__device__ __nv_bfloat16 g_Wqt_lo[768*CDIM];
__device__ __nv_bfloat16 g_Wpt_hi[CDIM*CDIM];
__device__ __nv_bfloat16 g_Wpt_lo[CDIM*CDIM];
__device__ __nv_bfloat16 g_attnhi[MROWS*CDIM];
__device__ __nv_bfloat16 g_attnlo[MROWS*CDIM];

// ---------- prep ----------
#define SEG0 (NPIX*NPAIR)
#define SEG1 (SEG0 + MROWS*CDIM)
#define SEG2 (SEG1 + 768*CDIM)
#define SEG3 (SEG2 + CDIM*CDIM)

__global__ void prep_kernel(const float* __restrict__ X, const float* __restrict__ Wq,
                            const float* __restrict__ Wp) {
    int idx = blockIdx.x * 256 + threadIdx.x;
    if (idx < SEG0) {
        int p = idx & 15, n = idx >> 4;
        double inv = pow(10000.0, -(double)p / 16.0);
        double s, c;
        sincos((double)n * inv, &s, &c);
        g_cos[idx] = (float)c; g_sin[idx] = (float)s;
    } else if (idx < SEG1) {
        int j = idx - SEG0;
        float x = X[j];
        __nv_bfloat16 hi = __float2bfloat16(x);
        g_Xhi[j] = hi; g_Xlo[j] = __float2bfloat16(x - __bfloat162float(hi));
    } else if (idx < SEG2) {
        int j = idx - SEG1;
        int n = j >> 8, k = j & 255;
        float x = Wq[k * 768 + n];
        __nv_bfloat16 hi = __float2bfloat16(x);
        g_Wqt_hi[j] = hi; g_Wqt_lo[j] = __float2bfloat16(x - __bfloat162float(hi));
    } else if (idx < SEG3) {
        int j = idx - SEG2;
        int n = j >> 8, k = j & 255;
        float x = Wp[k * 256 + n];
        __nv_bfloat16 hi = __float2bfloat16(x);
        g_Wpt_hi[j] = hi; g_Wpt_lo[j] = __float2bfloat16(x - __bfloat162float(hi));
    }
}

// ---------- mma helpers ----------
__device__ __forceinline__ void ldmatrix_x4(uint32_t* r, uint32_t addr) {
    asm volatile("ldmatrix.sync.aligned.m8n8.x4.shared.b16 {%0,%1,%2,%3}, [%4];"
                 : "=r"(r[0]), "=r"(r[1]), "=r"(r[2]), "=r"(r[3]) : "r"(addr));
}
__device__ __forceinline__ void mma16816(float* c, const uint32_t* a, uint32_t b0, uint32_t b1) {
    asm volatile("mma.sync.aligned.m16n8k16.row.col.f32.bf16.bf16.f32 "
                 "{%0,%1,%2,%3}, {%4,%5,%6,%7}, {%8,%9}, {%0,%1,%2,%3};"
                 : "+f"(c[0]), "+f"(c[1]), "+f"(c[2]), "+f"(c[3])
                 : "r"(a[0]), "r"(a[1]), "r"(a[2]), "r"(a[3]), "r"(b0), "r"(b1));
}
__device__ __forceinline__ void cp_async16(uint32_t dst, const void* src) {
    asm volatile("cp.async.cg.shared.global [%0], [%1], 16;" :: "r"(dst), "l"(src));
}
__device__ __forceinline__ void cp_commit() { asm volatile("cp.async.commit_group;"); }
template<int N> __device__ __forceinline__ void cp_wait() {
    asm volatile("cp.async.wait_group %0;" :: "n"(N) : "memory");
}

// ---------- GEMM: D[64x64] = A[64x256] @ B[64x256]^T, bf16 3-product split ----------
// 12 K-chunks of 64: chunk c -> product p=c>>2 (AhBh, AhBl, AlBh), kt=c&3.
// 3-stage cp.async pipeline; stage: A 64x72 bf16 (9216 B) + B 64x72 bf16 (9216 B).
#define A_TILE_B 9216
#define STAGE_B  18432
#define GEMM_SMEM (3*STAGE_B)

__global__ void __launch_bounds__(128, 4) gemm_mma(int mode, const float* __restrict__ bias,
                                                   float* __restrict__ out) {
    extern __shared__ __align__(16) __nv_bfloat16 smg[];
    const uint32_t sb = (uint32_t)__cvta_generic_to_shared(smg);

    const int tid = threadIdx.x, wid = tid >> 5, lane = tid & 31;
    const int warp_m = wid & 1, warp_n = wid >> 1;       // 2 x 2 warps
    const int mBase = blockIdx.y * 64, nBase = blockIdx.x * 64;

    const __nv_bfloat16 *Ah, *Al, *Bh, *Bl;
    if (mode) { Ah = g_attnhi; Al = g_attnlo; Bh = g_Wpt_hi; Bl = g_Wpt_lo; }
    else      { Ah = g_Xhi;    Al = g_Xlo;    Bh = g_Wqt_hi; Bl = g_Wqt_lo; }

    float acc[2][4][4];
#pragma unroll
    for (int i = 0; i < 2; i++)
#pragma unroll
        for (int j = 0; j < 4; j++)
#pragma unroll
            for (int k = 0; k < 4; k++) acc[i][j][k] = 0.f;

    uint32_t aoff[2], boff[2];
#pragma unroll
    for (int mi = 0; mi < 2; mi++)
        aoff[mi] = (uint32_t)(((warp_m * 32 + mi * 16 + (lane & 15)) * 72 + ((lane >> 4) << 3)) * 2);
#pragma unroll
    for (int np = 0; np < 2; np++)
        boff[np] = (uint32_t)(((warp_n * 32 + np * 16 + ((lane >> 4) << 3) + (lane & 7)) * 72 +
                               (((lane >> 3) & 1) << 3)) * 2);

    const int lkc = (tid & 7) << 3;

    auto issue = [&](int c) {
        const int p = c >> 2, kt = c & 3;
        const __nv_bfloat16* Asrc = (p == 2) ? Al : Ah;
        const __nv_bfloat16* Bsrc = (p == 1) ? Bl : Bh;
        const uint32_t s0 = sb + (uint32_t)(c % 3) * STAGE_B;
        const int kb = kt * 64 + lkc;
#pragma unroll
        for (int t = 0; t < 4; t++) {
            int r = (t * 128 + tid) >> 3;
            cp_async16(s0 + (uint32_t)((r * 72 + lkc) * 2),
                       Asrc + (size_t)(mBase + r) * 256 + kb);
            cp_async16(s0 + A_TILE_B + (uint32_t)((r * 72 + lkc) * 2),
                       Bsrc + (size_t)(nBase + r) * 256 + kb);
        }
        cp_commit();
    };

    issue(0); issue(1); issue(2);

    for (int c = 0; c < 12; c++) {
        if (c <= 9) cp_wait<2>(); else if (c == 10) cp_wait<1>(); else cp_wait<0>();
        __syncthreads();

        const uint32_t su = sb + (uint32_t)(c % 3) * STAGE_B;
#pragma unroll
        for (int kk = 0; kk < 4; kk++) {
            const uint32_t ko = kk * 32;
            uint32_t a[2][4], b[2][4];
#pragma unroll
            for (int mi = 0; mi < 2; mi++) ldmatrix_x4(a[mi], su + aoff[mi] + ko);
#pragma unroll
            for (int np = 0; np < 2; np++) ldmatrix_x4(b[np], su + A_TILE_B + boff[np] + ko);
#pragma unroll
            for (int mi = 0; mi < 2; mi++)
#pragma unroll
                for (int ni = 0; ni < 4; ni++)
                    mma16816(acc[mi][ni], a[mi], b[ni >> 1][(ni & 1) * 2], b[ni >> 1][(ni & 1) * 2 + 1]);
        }
        __syncthreads();
        if (c + 3 < 12) issue(c + 3);
    }

    // ---- epilogue ----
#pragma unroll
    for (int mi = 0; mi < 2; mi++) {
#pragma unroll
        for (int half = 0; half < 2; half++) {
            int grow = mBase + warp_m * 32 + mi * 16 + (lane >> 2) + half * 8;
            int b = (grow >= NPIX) ? 1 : 0;
            int nr = grow - b * NPIX;
            if (mode == 0) {
#pragma unroll
                for (int ni = 0; ni < 4; ni++) {
                    int gc = nBase + warp_n * 32 + ni * 8 + (lane & 3) * 2;
                    float x0 = acc[mi][ni][half * 2], x1 = acc[mi][ni][half * 2 + 1];
                    int which = gc >> 8;
                    int head = (gc >> 5) & 7;
                    int d0 = gc & 31;
                    float* dst = (which == 0) ? g_q : (which == 1) ? g_k : g_v;
                    if (which < 2) {
                        int p = d0 >> 1;
                        float cv = g_cos[nr * NPAIR + p], sv = g_sin[nr * NPAIR + p];
                        float o0 = x0 * cv - x1 * sv;
                        float o1 = x1 * cv + x0 * sv;
                        x0 = o0; x1 = o1;
                    }
                    *(float2*)&dst[((size_t)(b * HEADS + head) * NPIX + nr) * HD + d0] =
                        make_float2(x0, x1);
                }
            } else {
#pragma unroll
                for (int ni = 0; ni < 4; ni++) {
                    int gc = nBase + warp_n * 32 + ni * 8 + (lane & 3) * 2;
                    float2 bv = *(const float2*)&bias[gc];
                    *(float2*)&out[(size_t)grow * 256 + gc] =
                        make_float2(acc[mi][ni][half * 2] + bv.x,
                                    acc[mi][ni][half * 2 + 1] + bv.y);
                }
            }
        }
    }
}

// ---------- neighborhood attention: 2 query rows / block, K+V staged in smem ----------
// smem floats: ks[8*56*32=14336] vs[14336] sp[8*64]
#define ATT_VS 14336
#define ATT_SP 28672
#define ATTN_SMEM ((28672 + 512) * 4)

__global__ void __launch_bounds__(256) attn_kernel() {
    extern __shared__ float smf[];
    float* ks = smf;
    float* vs = smf + ATT_VS;
    float* sp = smf + ATT_SP;

    const int rp = blockIdx.x * 2;
    const int bh = blockIdx.y;
    const int tid = threadIdx.x, w = tid >> 5, lane = tid & 31;

    const int lo = min(max(rp - RAD, 0), HW - WIN);
    const int hi = min(max(rp + 1 - RAD, 0), HW - WIN);
    const int nrows = hi + WIN - lo;      // <= 8

    const float4* k4 = (const float4*)(g_k + ((size_t)bh * NPIX + lo * HW) * HD);
    const float4* v4 = (const float4*)(g_v + ((size_t)bh * NPIX + lo * HW) * HD);
    const int nf4 = nrows * HW * 8;
    for (int idx = tid; idx < nf4; idx += 256) {
        ((float4*)ks)[idx] = k4[idx];
        ((float4*)vs)[idx] = v4[idx];
    }
    __syncthreads();

    const float scale = 0.17677669529663688f;
    const int b = bh >> 3, h = bh & 7;

    const int kk0 = lane, kk1 = lane + 32;
    const int rr0 = kk0 / 7, cc0 = kk0 - rr0 * 7;
    const bool has1 = (kk1 < 49);
    const int rr1 = has1 ? kk1 / 7 : 0;
    const int cc1 = has1 ? (kk1 - rr1 * 7) : 0;

    for (int t = 0; t < 14; t++) {
        const int q_id = t * 8 + w;
        const int up = (q_id >= HW) ? 1 : 0;
        const int i = rp + up;
        const int col = q_id - up * HW;

        const float qv = g_q[((size_t)bh * NPIX + i * HW + col) * HD + lane];
        const int srow = min(max(i - RAD, 0), HW - WIN) - lo;
        const int c0 = min(max(col - RAD, 0), HW - WIN);
        const int off0 = ((srow + rr0) * HW + c0 + cc0) * HD;
        const int off1 = ((srow + rr1) * HW + c0 + cc1) * HD;

        float s0 = 0.f, s1 = 0.f;
#pragma unroll
        for (int d = 0; d < 32; d++) {
            int dd = (d + lane) & 31;
            float qd = __shfl_sync(0xffffffffu, qv, d + lane);
            s0 = fmaf(qd, ks[off0 + dd], s0);
            if (has1) s1 = fmaf(qd, ks[off1 + dd], s1);
        }
        s0 *= scale;
        s1 = has1 ? s1 * scale : -1e30f;

        float mx = fmaxf(s0, s1);
        mx = fmaxf(mx, __shfl_xor_sync(0xffffffffu, mx, 16));
        mx = fmaxf(mx, __shfl_xor_sync(0xffffffffu, mx, 8));
        mx = fmaxf(mx, __shfl_xor_sync(0xffffffffu, mx, 4));
        mx = fmaxf(mx, __shfl_xor_sync(0xffffffffu, mx, 2));
        mx = fmaxf(mx, __shfl_xor_sync(0xffffffffu, mx, 1));

        float p0 = __expf(s0 - mx);
        float p1 = has1 ? __expf(s1 - mx) : 0.f;
        float ls = p0 + p1;
        ls += __shfl_xor_sync(0xffffffffu, ls, 16);
        ls += __shfl_xor_sync(0xffffffffu, ls, 8);
        ls += __shfl_xor_sync(0xffffffffu, ls, 4);
        ls += __shfl_xor_sync(0xffffffffu, ls, 2);
        ls += __shfl_xor_sync(0xffffffffu, ls, 1);
        float inv = 1.0f / ls;

        sp[w * 64 + kk0] = p0 * inv;
        if (has1) sp[w * 64 + kk1] = p1 * inv;
        __syncwarp();

        float o = 0.f;
#pragma unroll
        for (int rr = 0; rr < WIN; rr++) {
            const float* vrow = vs + ((srow + rr) * HW + c0) * HD + lane;
#pragma unroll
            for (int cc = 0; cc < WIN; cc++) {
                o = fmaf(sp[w * 64 + rr * 7 + cc], vrow[cc * HD], o);
            }
        }
        size_t oi = ((size_t)b * NPIX + i * HW + col) * CDIM + h * HD + lane;
        __nv_bfloat16 hiv = __float2bfloat16(o);
        g_attnhi[oi] = hiv;
        g_attnlo[oi] = __float2bfloat16(o - __bfloat162float(hiv));
        __syncwarp();
    }
}

// ---------- launch ----------
extern "C" void kernel_launch(void* const* d_in, const int* in_sizes, int n_in,
                              void* d_out, int out_size) {
    const float* x     = (const float*)d_in[0];
    const float* Wqkv  = (const float*)d_in[1];
    const float* Wproj = (const float*)d_in[2];
    const float* bproj = (const float*)d_in[3];
    float* out = (float*)d_out;

    static bool attr_set = false;
    if (!attr_set) {
        cudaFuncSetAttribute(gemm_mma, cudaFuncAttributeMaxDynamicSharedMemorySize, GEMM_SMEM);
        cudaFuncSetAttribute(attn_kernel, cudaFuncAttributeMaxDynamicSharedMemorySize, ATTN_SMEM);
        attr_set = true;
    }

    prep_kernel<<<(SEG3 + 255) / 256, 256>>>(x, Wqkv, Wproj);
    gemm_mma<<<dim3(12, 98), 128, GEMM_SMEM>>>(0, bproj, out);
    attn_kernel<<<dim3(28, BATCH * HEADS), 256, ATTN_SMEM>>>();
    gemm_mma<<<dim3(4, 98), 128, GEMM_SMEM>>>(1, bproj, out);
}

// round 9
// speedup vs baseline: 1.4501x; 1.4501x over previous
#include <cuda_runtime.h>
#include <cuda_fp16.h>
#include <math.h>
#include <stdint.h>

#define HW    56
#define NPIX  3136
#define CDIM  256
#define HEADS 8
#define HD    32
#define NPAIR 16
#define BATCH 2
#define MROWS (BATCH*NPIX)
#define WIN   7
#define RAD   3

__device__ float g_q[BATCH*HEADS*NPIX*HD];
__device__ float g_k[BATCH*HEADS*NPIX*HD];
__device__ float g_v[BATCH*HEADS*NPIX*HD];
__device__ float g_cos[NPIX*NPAIR];
__device__ float g_sin[NPIX*NPAIR];
__device__ __half g_Xh[MROWS*CDIM];
__device__ __half g_Wqt[768*CDIM];     // transposed [n][k]
__device__ __half g_Wpt[CDIM*CDIM];    // transposed [n][k]
__device__ __half g_attn[MROWS*CDIM];

// ---------- prep: rope tables + fp16 casts + W transposes ----------
#define SEG0 (NPIX*NPAIR)
#define SEG1 (SEG0 + MROWS*CDIM)
#define SEG2 (SEG1 + 768*CDIM)
#define SEG3 (SEG2 + CDIM*CDIM)

__global__ void prep_kernel(const float* __restrict__ X, const float* __restrict__ Wq,
                            const float* __restrict__ Wp) {
    int idx = blockIdx.x * 256 + threadIdx.x;
    if (idx < SEG0) {
        int p = idx & 15, n = idx >> 4;
        double inv = pow(10000.0, -(double)p / 16.0);
        double s, c;
        sincos((double)n * inv, &s, &c);
        g_cos[idx] = (float)c; g_sin[idx] = (float)s;
    } else if (idx < SEG1) {
        int j = idx - SEG0;
        g_Xh[j] = __float2half(X[j]);
    } else if (idx < SEG2) {
        int j = idx - SEG1;
        int n = j >> 8, k = j & 255;
        g_Wqt[j] = __float2half(Wq[k * 768 + n]);
    } else if (idx < SEG3) {
        int j = idx - SEG2;
        int n = j >> 8, k = j & 255;
        g_Wpt[j] = __float2half(Wp[k * 256 + n]);
    }
}

// ---------- mma helpers ----------
__device__ __forceinline__ void ldmatrix_x4(uint32_t* r, uint32_t addr) {
    asm volatile("ldmatrix.sync.aligned.m8n8.x4.shared.b16 {%0,%1,%2,%3}, [%4];"
                 : "=r"(r[0]), "=r"(r[1]), "=r"(r[2]), "=r"(r[3]) : "r"(addr));
}
__device__ __forceinline__ void mma16816(float* c, const uint32_t* a, uint32_t b0, uint32_t b1) {
    asm volatile("mma.sync.aligned.m16n8k16.row.col.f32.f16.f16.f32 "
                 "{%0,%1,%2,%3}, {%4,%5,%6,%7}, {%8,%9}, {%0,%1,%2,%3};"
                 : "+f"(c[0]), "+f"(c[1]), "+f"(c[2]), "+f"(c[3])
                 : "r"(a[0]), "r"(a[1]), "r"(a[2]), "r"(a[3]), "r"(b0), "r"(b1));
}
__device__ __forceinline__ void cp_async16(uint32_t dst, const void* src) {
    asm volatile("cp.async.cg.shared.global [%0], [%1], 16;" :: "r"(dst), "l"(src));
}
__device__ __forceinline__ void cp_commit() { asm volatile("cp.async.commit_group;"); }
template<int N> __device__ __forceinline__ void cp_wait() {
    asm volatile("cp.async.wait_group %0;" :: "n"(N) : "memory");
}

// ---------- GEMM: D[128x64] = A[128x256] @ B[64x256]^T, single fp16 product ----------
// 4 K-chunks of 64; 3-stage cp.async pipeline.
// stage: A 128x72 fp16 (18432 B) + B 64x72 fp16 (9216 B) = 27648 B.
#define A_TILE_B 18432
#define STAGE_B  27648
#define GEMM_SMEM (3*STAGE_B)

__global__ void __launch_bounds__(256, 2) gemm_mma(int mode, const float* __restrict__ bias,
                                                   float* __restrict__ out) {
    extern __shared__ __align__(16) __half smg[];
    const uint32_t sb = (uint32_t)__cvta_generic_to_shared(smg);

    const int tid = threadIdx.x, wid = tid >> 5, lane = tid & 31;
    const int warp_m = wid & 3, warp_n = wid >> 2;       // 4 x 2
    const int mBase = blockIdx.y * 128, nBase = blockIdx.x * 64;

    const __half* A = mode ? g_attn : g_Xh;
    const __half* B = mode ? g_Wpt  : g_Wqt;

    float acc[2][4][4];
#pragma unroll
    for (int i = 0; i < 2; i++)
#pragma unroll
        for (int j = 0; j < 4; j++)
#pragma unroll
            for (int k = 0; k < 4; k++) acc[i][j][k] = 0.f;

    uint32_t aoff[2], boff[2];
#pragma unroll
    for (int mi = 0; mi < 2; mi++)
        aoff[mi] = (uint32_t)(((warp_m * 32 + mi * 16 + (lane & 15)) * 72 + ((lane >> 4) << 3)) * 2);
#pragma unroll
    for (int np = 0; np < 2; np++)
        boff[np] = (uint32_t)(((warp_n * 32 + np * 16 + ((lane >> 4) << 3) + (lane & 7)) * 72 +
                               (((lane >> 3) & 1) << 3)) * 2);

    const int lkc = (tid & 7) << 3;

    auto issue = [&](int c) {
        const uint32_t s0 = sb + (uint32_t)(c % 3) * STAGE_B;
        const int kb = c * 64 + lkc;
#pragma unroll
        for (int t = 0; t < 4; t++) {
            int r = (t * 256 + tid) >> 3;
            cp_async16(s0 + (uint32_t)((r * 72 + lkc) * 2),
                       A + (size_t)(mBase + r) * 256 + kb);
        }
#pragma unroll
        for (int t = 0; t < 2; t++) {
            int r = (t * 256 + tid) >> 3;
            cp_async16(s0 + A_TILE_B + (uint32_t)((r * 72 + lkc) * 2),
                       B + (size_t)(nBase + r) * 256 + kb);
        }
        cp_commit();
    };

    issue(0); issue(1); issue(2);

    for (int c = 0; c < 4; c++) {
        if (c <= 1) cp_wait<2>(); else if (c == 2) cp_wait<1>(); else cp_wait<0>();
        __syncthreads();

        const uint32_t su = sb + (uint32_t)(c % 3) * STAGE_B;
#pragma unroll
        for (int kk = 0; kk < 4; kk++) {
            const uint32_t ko = kk * 32;
            uint32_t a[2][4], b[2][4];
#pragma unroll
            for (int mi = 0; mi < 2; mi++) ldmatrix_x4(a[mi], su + aoff[mi] + ko);
#pragma unroll
            for (int np = 0; np < 2; np++) ldmatrix_x4(b[np], su + A_TILE_B + boff[np] + ko);
#pragma unroll
            for (int mi = 0; mi < 2; mi++)
#pragma unroll
                for (int ni = 0; ni < 4; ni++)
                    mma16816(acc[mi][ni], a[mi], b[ni >> 1][(ni & 1) * 2], b[ni >> 1][(ni & 1) * 2 + 1]);
        }
        __syncthreads();
        if (c + 3 < 4) issue(c + 3);
    }

    // ---- epilogue ----
#pragma unroll
    for (int mi = 0; mi < 2; mi++) {
#pragma unroll
        for (int half = 0; half < 2; half++) {
            int grow = mBase + warp_m * 32 + mi * 16 + (lane >> 2) + half * 8;
            int b = (grow >= NPIX) ? 1 : 0;
            int nr = grow - b * NPIX;
            if (mode == 0) {
#pragma unroll
                for (int ni = 0; ni < 4; ni++) {
                    int gc = nBase + warp_n * 32 + ni * 8 + (lane & 3) * 2;
                    float x0 = acc[mi][ni][half * 2], x1 = acc[mi][ni][half * 2 + 1];
                    int which = gc >> 8;
                    int head = (gc >> 5) & 7;
                    int d0 = gc & 31;
                    float* dst = (which == 0) ? g_q : (which == 1) ? g_k : g_v;
                    if (which < 2) {
                        int p = d0 >> 1;
                        float cv = g_cos[nr * NPAIR + p], sv = g_sin[nr * NPAIR + p];
                        float o0 = x0 * cv - x1 * sv;
                        float o1 = x1 * cv + x0 * sv;
                        x0 = o0; x1 = o1;
                    }
                    *(float2*)&dst[((size_t)(b * HEADS + head) * NPIX + nr) * HD + d0] =
                        make_float2(x0, x1);
                }
            } else {
#pragma unroll
                for (int ni = 0; ni < 4; ni++) {
                    int gc = nBase + warp_n * 32 + ni * 8 + (lane & 3) * 2;
                    float2 bv = *(const float2*)&bias[gc];
                    *(float2*)&out[(size_t)grow * 256 + gc] =
                        make_float2(acc[mi][ni][half * 2] + bv.x,
                                    acc[mi][ni][half * 2 + 1] + bv.y);
                }
            }
        }
    }
}

// ---------- neighborhood attention: 2 query rows / block, K staged, V direct (R6 config) ----------
#define ATT_SP 14336
#define ATTN_SMEM ((14336 + 512) * 4)

__global__ void __launch_bounds__(256) attn_kernel() {
    extern __shared__ float smf[];
    float* ks = smf;
    float* sp = smf + ATT_SP;

    const int rp = blockIdx.x * 2;
    const int bh = blockIdx.y;
    const int tid = threadIdx.x, w = tid >> 5, lane = tid & 31;

    const int lo = min(max(rp - RAD, 0), HW - WIN);
    const int hi = min(max(rp + 1 - RAD, 0), HW - WIN);
    const int nrows = hi + WIN - lo;

    const float4* k4 = (const float4*)(g_k + ((size_t)bh * NPIX + lo * HW) * HD);
    const int nf4 = nrows * HW * 8;
    for (int idx = tid; idx < nf4; idx += 256) ((float4*)ks)[idx] = k4[idx];
    __syncthreads();

    const float scale = 0.17677669529663688f;
    const int b = bh >> 3, h = bh & 7;
    const float* gvb = g_v + (size_t)bh * NPIX * HD;

    const int kk0 = lane, kk1 = lane + 32;
    const int rr0 = kk0 / 7, cc0 = kk0 - rr0 * 7;
    const bool has1 = (kk1 < 49);
    const int rr1 = has1 ? kk1 / 7 : 0;
    const int cc1 = has1 ? (kk1 - rr1 * 7) : 0;

    for (int t = 0; t < 14; t++) {
        const int q_id = t * 8 + w;
        const int up = (q_id >= HW) ? 1 : 0;
        const int i = rp + up;
        const int col = q_id - up * HW;

        const float qv = g_q[((size_t)bh * NPIX + i * HW + col) * HD + lane];
        const int srow = min(max(i - RAD, 0), HW - WIN) - lo;
        const int c0 = min(max(col - RAD, 0), HW - WIN);
        const int off0 = ((srow + rr0) * HW + c0 + cc0) * HD;
        const int off1 = ((srow + rr1) * HW + c0 + cc1) * HD;

        float s0 = 0.f, s1 = 0.f;
#pragma unroll
        for (int d = 0; d < 32; d++) {
            int dd = (d + lane) & 31;
            float qd = __shfl_sync(0xffffffffu, qv, d + lane);
            s0 = fmaf(qd, ks[off0 + dd], s0);
            s1 = fmaf(qd, ks[off1 + dd], s1);
        }
        s0 *= scale;
        s1 = has1 ? s1 * scale : -1e30f;

        float mx = fmaxf(s0, s1);
        mx = fmaxf(mx, __shfl_xor_sync(0xffffffffu, mx, 16));
        mx = fmaxf(mx, __shfl_xor_sync(0xffffffffu, mx, 8));
        mx = fmaxf(mx, __shfl_xor_sync(0xffffffffu, mx, 4));
        mx = fmaxf(mx, __shfl_xor_sync(0xffffffffu, mx, 2));
        mx = fmaxf(mx, __shfl_xor_sync(0xffffffffu, mx, 1));

        float p0 = __expf(s0 - mx);
        float p1 = has1 ? __expf(s1 - mx) : 0.f;
        float ls = p0 + p1;
        ls += __shfl_xor_sync(0xffffffffu, ls, 16);
        ls += __shfl_xor_sync(0xffffffffu, ls, 8);
        ls += __shfl_xor_sync(0xffffffffu, ls, 4);
        ls += __shfl_xor_sync(0xffffffffu, ls, 2);
        ls += __shfl_xor_sync(0xffffffffu, ls, 1);
        float inv = 1.0f / ls;

        sp[w * 64 + kk0] = p0 * inv;
        if (has1) sp[w * 64 + kk1] = p1 * inv;
        __syncwarp();

        float o = 0.f;
#pragma unroll
        for (int rr = 0; rr < WIN; rr++) {
            const float* vrow = gvb + ((size_t)(lo + srow + rr) * HW + c0) * HD + lane;
#pragma unroll
            for (int cc = 0; cc < WIN; cc++) {
                o = fmaf(sp[w * 64 + rr * 7 + cc], vrow[cc * HD], o);
            }
        }
        size_t oi = ((size_t)b * NPIX + i * HW + col) * CDIM + h * HD + lane;
        g_attn[oi] = __float2half(o);
        __syncwarp();
    }
}

// ---------- launch ----------
extern "C" void kernel_launch(void* const* d_in, const int* in_sizes, int n_in,
                              void* d_out, int out_size) {
    const float* x     = (const float*)d_in[0];
    const float* Wqkv  = (const float*)d_in[1];
    const float* Wproj = (const float*)d_in[2];
    const float* bproj = (const float*)d_in[3];
    float* out = (float*)d_out;

    static bool attr_set = false;
    if (!attr_set) {
        cudaFuncSetAttribute(gemm_mma, cudaFuncAttributeMaxDynamicSharedMemorySize, GEMM_SMEM);
        cudaFuncSetAttribute(attn_kernel, cudaFuncAttributeMaxDynamicSharedMemorySize, ATTN_SMEM);
        attr_set = true;
    }

    prep_kernel<<<(SEG3 + 255) / 256, 256>>>(x, Wqkv, Wproj);
    gemm_mma<<<dim3(12, 49), 256, GEMM_SMEM>>>(0, bproj, out);
    attn_kernel<<<dim3(28, BATCH * HEADS), 256, ATTN_SMEM>>>();
    gemm_mma<<<dim3(4, 49), 256, GEMM_SMEM>>>(1, bproj, out);
}